// round 13
// baseline (speedup 1.0000x reference)
#include <cuda_runtime.h>
#include <cstdint>
#include <cstddef>

// RecurrentPrediction: h[B,T,1] -> out[B,C,T], C=3 tanh-RNN. B=2048, T=4096.
//
// R13: R12 (MUFU.TANH, 32.8us, rel_err 4.7e-6 — 200x under gate) + KC=64.
// R12 profile: issue 28.3% -> purely exposed-latency bound; empty issue slots
// abound, so doubling resident warps (4096 blocks, ~18/SM) should fill them.
// Chunk 64 + WARM 16 = 80 steps/warp. Everything else identical to R12.
// KC chunks, UT=16 cp.async double-buffered staging, stride-5 conflict-free
// smem transposes, 12 coalesced STG.128 per unit, hardware tanh.

#define B_TOTAL 2048
#define T_LEN   4096
#define KC      64
#define CHUNK   (T_LEN / KC)     // 64
#define WARM    16
#define UT      16               // unit (time steps)

__device__ __forceinline__ float tanh_hw(float x) {
    float r;
    asm("tanh.approx.f32 %0, %1;" : "=f"(r) : "f"(x));
    return r;
}

__device__ __forceinline__ void cp_async16(uint32_t dst, const float* src) {
    asm volatile("cp.async.cg.shared.global [%0], [%1], 16;" :: "r"(dst), "l"(src));
}

__global__ void __launch_bounds__(32, 24)
rnn_chunk_kernel(const float* __restrict__ h,
                 const float* __restrict__ W_ih,
                 const float* __restrict__ W_hh,
                 const float* __restrict__ b_ih,
                 const float* __restrict__ b_hh,
                 float* __restrict__ out)
{
    // input: [buf][chain][time-quad], stride 5 float4 (16 steps + pad)
    __shared__ float4 sin4[2][32][5];    // 5.0 KB
    // output: [channel][chain][time-quad], stride 5 float4
    __shared__ float4 sout4[3][32][5];   // 7.5 KB

    const int lane = threadIdx.x;
    const int kc   = blockIdx.x & (KC - 1);
    const int b0   = (blockIdx.x >> 6) * 32;
    const float* hrow = h + (size_t)b0 * T_LEN;

    const int t_write = kc * CHUNK;
    const int t_begin = (t_write >= WARM) ? (t_write - WARM) : 0;
    const int nunits  = (t_write + CHUNK - t_begin) / UT;   // 4 or 5

    const float wi00 = W_ih[0], wi01 = W_ih[1];
    const float wi10 = W_ih[2], wi11 = W_ih[3];
    const float wi20 = W_ih[4], wi21 = W_ih[5];
    const float wA0 = wi00 + wi01, wB0 = -wi01;
    const float wA1 = wi10 + wi11, wB1 = -wi11;
    const float wA2 = wi20 + wi21, wB2 = -wi21;
    const float bb0 = b_ih[0] + b_hh[0];
    const float bb1 = b_ih[1] + b_hh[1];
    const float bb2 = b_ih[2] + b_hh[2];
    const float G00 = W_hh[0], G01 = W_hh[1], G02 = W_hh[2];
    const float G10 = W_hh[3], G11 = W_hh[4], G12 = W_hh[5];
    const float G20 = W_hh[6], G21 = W_hh[7], G22 = W_hh[8];

    float s0 = 0.f, s1 = 0.f, s2 = 0.f;
    float hprev = (t_begin == 0) ? 0.f
                : hrow[(size_t)lane * T_LEN + (t_begin - 1)];

    const uint32_t sin_s = (uint32_t)__cvta_generic_to_shared(&sin4[0][0][0]);
    const int rq = lane >> 2;        // 0..7
    const int qq = lane & 3;         // 0..3

    // incremental global pointers
    const float* gp0 = hrow + (size_t)(8 * 0 + rq) * T_LEN + t_begin + qq * 4;
    const float* gp1 = hrow + (size_t)(8 * 1 + rq) * T_LEN + t_begin + qq * 4;
    const float* gp2 = hrow + (size_t)(8 * 2 + rq) * T_LEN + t_begin + qq * 4;
    const float* gp3 = hrow + (size_t)(8 * 3 + rq) * T_LEN + t_begin + qq * 4;
    float* op0 = out + ((size_t)(b0 + rq) * 3 + 0) * T_LEN + t_write + qq * 4;
    float* op1 = op0 + T_LEN;
    float* op2 = op1 + T_LEN;

    const uint32_t sdst = sin_s + (uint32_t)(rq * 80 + qq * 16);

    #define PREFETCH(NB)                                                     \
        {                                                                    \
            const uint32_t d = sdst + (uint32_t)(NB) * 2560u;                \
            cp_async16(d,          gp0);                                     \
            cp_async16(d + 640u,   gp1);                                     \
            cp_async16(d + 1280u,  gp2);                                     \
            cp_async16(d + 1920u,  gp3);                                     \
            gp0 += UT; gp1 += UT; gp2 += UT; gp3 += UT;                      \
            asm volatile("cp.async.commit_group;");                          \
        }

    #define STEP(HT, O0, O1, O2)                                             \
        {                                                                    \
            const float ht = (HT);                                           \
            float p0 = fmaf(wA0, ht, fmaf(wB0, hprev, bb0));                 \
            float p1 = fmaf(wA1, ht, fmaf(wB1, hprev, bb1));                 \
            float p2 = fmaf(wA2, ht, fmaf(wB2, hprev, bb2));                 \
            hprev = ht;                                                      \
            float a0 = fmaf(G00, s0, fmaf(G01, s1, fmaf(G02, s2, p0)));      \
            float a1 = fmaf(G11, s1, fmaf(G10, s0, fmaf(G12, s2, p1)));      \
            float a2 = fmaf(G22, s2, fmaf(G20, s0, fmaf(G21, s1, p2)));      \
            s0 = tanh_hw(a0);                                                \
            s1 = tanh_hw(a1);                                                \
            s2 = tanh_hw(a2);                                                \
            O0 = s0; O1 = s1; O2 = s2;                                       \
        }

    PREFETCH(0);

    for (int u = 0; u < nunits; ++u) {
        const int t0 = t_begin + u * UT;

        if (u + 1 < nunits) {
            PREFETCH((u + 1) & 1);
            asm volatile("cp.async.wait_group 1;");
        } else {
            asm volatile("cp.async.wait_group 0;");
        }
        __syncwarp();

        const float4* sl = &sin4[u & 1][lane][0];
        float4 q0 = sl[0];
        float4 q1 = sl[1];
        float4 q2 = sl[2];
        float4 q3 = sl[3];

        if (t0 >= t_write) {
            float4 o0, o1, o2;
            #define QUAD(Q, K)                                               \
                STEP(Q.x, o0.x, o1.x, o2.x)                                  \
                STEP(Q.y, o0.y, o1.y, o2.y)                                  \
                STEP(Q.z, o0.z, o1.z, o2.z)                                  \
                STEP(Q.w, o0.w, o1.w, o2.w)                                  \
                sout4[0][lane][K] = o0;                                      \
                sout4[1][lane][K] = o1;                                      \
                sout4[2][lane][K] = o2;
            QUAD(q0, 0) QUAD(q1, 1) QUAD(q2, 2) QUAD(q3, 3)
            #undef QUAD
            __syncwarp();

            #pragma unroll
            for (int g = 0; g < 4; ++g) {
                const size_t roff = (size_t)g * (24 * T_LEN);
                *(float4*)(op0 + roff) = sout4[0][rq + 8 * g][qq];
                *(float4*)(op1 + roff) = sout4[1][rq + 8 * g][qq];
                *(float4*)(op2 + roff) = sout4[2][rq + 8 * g][qq];
            }
            op0 += UT; op1 += UT; op2 += UT;
            __syncwarp();
        } else {
            float d0, d1, d2;
            #define QUADW(Q)                                                 \
                STEP(Q.x, d0, d1, d2) STEP(Q.y, d0, d1, d2)                  \
                STEP(Q.z, d0, d1, d2) STEP(Q.w, d0, d1, d2)
            QUADW(q0) QUADW(q1) QUADW(q2) QUADW(q3)
            #undef QUADW
        }
    }
    #undef STEP
    #undef PREFETCH
}

extern "C" void kernel_launch(void* const* d_in, const int* in_sizes, int n_in,
                              void* d_out, int out_size)
{
    const float* h    = (const float*)d_in[0];
    const float* W_ih = (const float*)d_in[1];
    const float* W_hh = (const float*)d_in[2];
    const float* b_ih = (const float*)d_in[3];
    const float* b_hh = (const float*)d_in[4];
    float* out = (float*)d_out;

    rnn_chunk_kernel<<<(B_TOTAL / 32) * KC, 32>>>(h, W_ih, W_hh, b_ih, b_hh, out);
}

// round 14
// speedup vs baseline: 1.2803x; 1.2803x over previous
#include <cuda_runtime.h>
#include <cstdint>
#include <cstddef>

// RecurrentPrediction: h[B,T,1] -> out[B,C,T], C=3 tanh-RNN. B=2048, T=4096.
//
// R14: R12 (best, 32.8us) + 3-deep cp.async prefetch ring. R12's dominant
// stall: prefetch for unit u+1 issued at unit u and waited one unit later --
// only ~450cy slack vs ~600-1000cy loaded L2/DRAM latency, so warps parked in
// wait_group at almost every boundary (issue 28%). Ring depth 3 gives each
// prefetch ~2 units of flight. KC=32 chunks of 128, WARM=16, UT=16,
// stride-5 conflict-free smem transposes, 12 coalesced STG.128 per unit,
// hardware tanh (MUFU.TANH).

#define B_TOTAL 2048
#define T_LEN   4096
#define KC      32
#define CHUNK   (T_LEN / KC)     // 128
#define WARM    16
#define UT      16               // unit (time steps)

__device__ __forceinline__ float tanh_hw(float x) {
    float r;
    asm("tanh.approx.f32 %0, %1;" : "=f"(r) : "f"(x));
    return r;
}

__device__ __forceinline__ void cp_async16(uint32_t dst, const float* src) {
    asm volatile("cp.async.cg.shared.global [%0], [%1], 16;" :: "r"(dst), "l"(src));
}

__global__ void __launch_bounds__(32, 15)
rnn_chunk_kernel(const float* __restrict__ h,
                 const float* __restrict__ W_ih,
                 const float* __restrict__ W_hh,
                 const float* __restrict__ b_ih,
                 const float* __restrict__ b_hh,
                 float* __restrict__ out)
{
    // input ring: [buf(3)][chain][time-quad], stride 5 float4
    __shared__ float4 sin4[3][32][5];    // 7.5 KB
    // output: [channel][chain][time-quad], stride 5 float4
    __shared__ float4 sout4[3][32][5];   // 7.5 KB

    const int lane = threadIdx.x;
    const int kc   = blockIdx.x & (KC - 1);
    const int b0   = (blockIdx.x >> 5) * 32;
    const float* hrow = h + (size_t)b0 * T_LEN;

    const int t_write = kc * CHUNK;
    const int t_begin = (t_write >= WARM) ? (t_write - WARM) : 0;
    const int nunits  = (t_write + CHUNK - t_begin) / UT;   // 8 or 9

    const float wi00 = W_ih[0], wi01 = W_ih[1];
    const float wi10 = W_ih[2], wi11 = W_ih[3];
    const float wi20 = W_ih[4], wi21 = W_ih[5];
    const float wA0 = wi00 + wi01, wB0 = -wi01;
    const float wA1 = wi10 + wi11, wB1 = -wi11;
    const float wA2 = wi20 + wi21, wB2 = -wi21;
    const float bb0 = b_ih[0] + b_hh[0];
    const float bb1 = b_ih[1] + b_hh[1];
    const float bb2 = b_ih[2] + b_hh[2];
    const float G00 = W_hh[0], G01 = W_hh[1], G02 = W_hh[2];
    const float G10 = W_hh[3], G11 = W_hh[4], G12 = W_hh[5];
    const float G20 = W_hh[6], G21 = W_hh[7], G22 = W_hh[8];

    float s0 = 0.f, s1 = 0.f, s2 = 0.f;
    float hprev = (t_begin == 0) ? 0.f
                : hrow[(size_t)lane * T_LEN + (t_begin - 1)];

    const uint32_t sin_s = (uint32_t)__cvta_generic_to_shared(&sin4[0][0][0]);
    const int rq = lane >> 2;        // 0..7
    const int qq = lane & 3;         // 0..3

    // incremental global pointers (advance +UT floats per issued prefetch)
    const float* gp0 = hrow + (size_t)(8 * 0 + rq) * T_LEN + t_begin + qq * 4;
    const float* gp1 = hrow + (size_t)(8 * 1 + rq) * T_LEN + t_begin + qq * 4;
    const float* gp2 = hrow + (size_t)(8 * 2 + rq) * T_LEN + t_begin + qq * 4;
    const float* gp3 = hrow + (size_t)(8 * 3 + rq) * T_LEN + t_begin + qq * 4;
    float* op0 = out + ((size_t)(b0 + rq) * 3 + 0) * T_LEN + t_write + qq * 4;
    float* op1 = op0 + T_LEN;
    float* op2 = op1 + T_LEN;

    const uint32_t sdst = sin_s + (uint32_t)(rq * 80 + qq * 16);

    #define PREFETCH(NB)                                                     \
        {                                                                    \
            const uint32_t d = sdst + (uint32_t)(NB) * 2560u;                \
            cp_async16(d,          gp0);                                     \
            cp_async16(d + 640u,   gp1);                                     \
            cp_async16(d + 1280u,  gp2);                                     \
            cp_async16(d + 1920u,  gp3);                                     \
            gp0 += UT; gp1 += UT; gp2 += UT; gp3 += UT;                      \
            asm volatile("cp.async.commit_group;");                          \
        }

    #define STEP(HT, O0, O1, O2)                                             \
        {                                                                    \
            const float ht = (HT);                                           \
            float p0 = fmaf(wA0, ht, fmaf(wB0, hprev, bb0));                 \
            float p1 = fmaf(wA1, ht, fmaf(wB1, hprev, bb1));                 \
            float p2 = fmaf(wA2, ht, fmaf(wB2, hprev, bb2));                 \
            hprev = ht;                                                      \
            float a0 = fmaf(G00, s0, fmaf(G01, s1, fmaf(G02, s2, p0)));      \
            float a1 = fmaf(G11, s1, fmaf(G10, s0, fmaf(G12, s2, p1)));      \
            float a2 = fmaf(G22, s2, fmaf(G20, s0, fmaf(G21, s1, p2)));      \
            s0 = tanh_hw(a0);                                                \
            s1 = tanh_hw(a1);                                                \
            s2 = tanh_hw(a2);                                                \
            O0 = s0; O1 = s1; O2 = s2;                                       \
        }

    // Prologue: prefetch units 0 and 1 (buffers 0 and 1).
    PREFETCH(0);
    if (nunits > 1) PREFETCH(1);

    int buf = 0;                 // buffer of current unit (u % 3)
    for (int u = 0; u < nunits; ++u) {
        const int t0 = t_begin + u * UT;

        if (u + 2 < nunits) {
            // issue u+2 into buffer (u+2)%3, then wait for u's group
            const int nb = (buf + 2 >= 3) ? (buf - 1) : (buf + 2);
            PREFETCH(nb);
            asm volatile("cp.async.wait_group 2;");
        } else if (u + 1 < nunits) {
            asm volatile("cp.async.wait_group 1;");
        } else {
            asm volatile("cp.async.wait_group 0;");
        }
        __syncwarp();

        const float4* sl = &sin4[buf][lane][0];
        float4 q0 = sl[0];
        float4 q1 = sl[1];
        float4 q2 = sl[2];
        float4 q3 = sl[3];

        if (t0 >= t_write) {
            float4 o0, o1, o2;
            #define QUAD(Q, K)                                               \
                STEP(Q.x, o0.x, o1.x, o2.x)                                  \
                STEP(Q.y, o0.y, o1.y, o2.y)                                  \
                STEP(Q.z, o0.z, o1.z, o2.z)                                  \
                STEP(Q.w, o0.w, o1.w, o2.w)                                  \
                sout4[0][lane][K] = o0;                                      \
                sout4[1][lane][K] = o1;                                      \
                sout4[2][lane][K] = o2;
            QUAD(q0, 0) QUAD(q1, 1) QUAD(q2, 2) QUAD(q3, 3)
            #undef QUAD
            __syncwarp();

            #pragma unroll
            for (int g = 0; g < 4; ++g) {
                const size_t roff = (size_t)g * (24 * T_LEN);
                *(float4*)(op0 + roff) = sout4[0][rq + 8 * g][qq];
                *(float4*)(op1 + roff) = sout4[1][rq + 8 * g][qq];
                *(float4*)(op2 + roff) = sout4[2][rq + 8 * g][qq];
            }
            op0 += UT; op1 += UT; op2 += UT;
            __syncwarp();
        } else {
            float d0, d1, d2;
            #define QUADW(Q)                                                 \
                STEP(Q.x, d0, d1, d2) STEP(Q.y, d0, d1, d2)                  \
                STEP(Q.z, d0, d1, d2) STEP(Q.w, d0, d1, d2)
            QUADW(q0) QUADW(q1) QUADW(q2) QUADW(q3)
            #undef QUADW
        }

        buf = (buf + 1 >= 3) ? 0 : (buf + 1);
    }
    #undef STEP
    #undef PREFETCH
}

extern "C" void kernel_launch(void* const* d_in, const int* in_sizes, int n_in,
                              void* d_out, int out_size)
{
    const float* h    = (const float*)d_in[0];
    const float* W_ih = (const float*)d_in[1];
    const float* W_hh = (const float*)d_in[2];
    const float* b_ih = (const float*)d_in[3];
    const float* b_hh = (const float*)d_in[4];
    float* out = (float*)d_out;

    rnn_chunk_kernel<<<(B_TOTAL / 32) * KC, 32>>>(h, W_ih, W_hh, b_ih, b_hh, out);
}